// round 13
// baseline (speedup 1.0000x reference)
#include <cuda_runtime.h>
#include <math.h>
#include <stdint.h>

// Problem constants: B=64, C=8, H=256, M=32  -> B*C=512 images, 1024 modes/image
#define NIMG   512
#define NMODE  1024
#define NBIG   (NIMG * NMODE)          // 524288

// Output layout (tuple order, concatenated float32):
#define OFF_E    ((size_t)0)
#define OFF_U    ((size_t)NBIG)
#define OFF_F    ((size_t)(2*NBIG))
#define OFF_W    ((size_t)(3*NBIG))
#define OFF_US   ((size_t)(4*NBIG))
#define OFF_ES   ((size_t)(4*NBIG + 1024))
#define OFF_ERR  ((size_t)(4*NBIG + 2048))
#define OFF_CAL  ((size_t)(5*NBIG + 2048))

#define EPS 1e-8f

typedef unsigned long long ull;

// packed f32x2 helpers (FFMA2 is PTX-only; ptxas never emits it from C++)
#define FMA2(d, a, b, c) \
    asm("fma.rn.f32x2 %0, %1, %2, %3;" : "=l"(d) : "l"(a), "l"(b), "l"(c))
#define PACK2(d, lo, hi) \
    asm("mov.b64 %0, {%1, %2};" : "=l"(d) : "f"(lo), "f"(hi))
#define UNPACK2(lo, hi, s) \
    asm("mov.b64 {%0, %1}, %2;" : "=f"(lo), "=f"(hi) : "l"(s))

// Scratch: 32x32 complex modes for pred (tensor 0) and gt (tensor 1)
__device__ float g_modesR[2 * NIMG * NMODE];
__device__ float g_modesI[2 * NIMG * NMODE];

// ---------------------------------------------------------------------------
// Kernel 1: pruned 2-D DFT. One block per (tensor, image).
// 16 chunks x 16 rows; ~21 KB static smem -> 4 blocks/SM (warp-limited).
//
// Fold (per row, y=1..63): with s_y=f[y]+f[256-y], d_y=f[y]-f[256-y]:
//   fe[y] = ( s_y+s_{128-y}, -(d_y-d_{128-y}) )   (feeds even k2)
//   fo[y] = ( s_y-s_{128-y}, -(d_y+d_{128-y}) )   (feeds odd  k2)
// Stage 1 (lane=k2): acc(f32x2) += fe/fo[y] * (cos,sin) — 1 FFMA2 per (row,y).
//   Init even: (f0+f128+(-1)^{k/2} s64, 0); odd: (f0-f128, -(-1)^{(k-1)/2} d64).
// Stage 2: A += G*c, B += G*s (packed complex); F = A - iB at the end.
// Twiddles via phase recurrences seeded with sincospif (exact args).
// ---------------------------------------------------------------------------
#define CROWS   16
#define NCHUNK  16
#define FO_OFF  2052                       // floats; 8208 B => +4 banks vs fe
#define GC_STRIDE 68                       // floats per Gc row (32 complex + 2 pad)

__global__ __launch_bounds__(256, 4) void fft_kernel(const float* __restrict__ pred,
                                                     const float* __restrict__ gt) {
    __shared__ __align__(16) float fold[2 * 2052];        // fe @0, fo @FO_OFF (16416 B)
    __shared__ float4 spv[CROWS];                          // {f0, f128, s64, d64}
    __shared__ __align__(16) float Gc[CROWS * GC_STRIDE];  // interleaved (re,im) 4352 B

    const int blk = blockIdx.x;                          // tensor*512 + img
    const float* src = ((blk >> 9) ? gt : pred) + (size_t)(blk & 511) * 65536u;

    const int t    = threadIdx.x;
    const int w    = t >> 5;
    const int lane = t & 31;                             // lane == k2 (stage 1)
    const int rbase = w * 2;                             // 2 rows per warp per chunk

    // stage-1 twiddle seeds
    float ck, sk;
    sincospif((float)lane * (1.0f / 128.0f), &sk, &ck);  // cis(theta), theta=2pi*k2/256
    const float c2k = ck * ck - sk * sk;                 // cis(2*theta)
    const float s2k = 2.0f * sk * ck;
    const int   par = lane & 1;
    const float sg  = (lane & 2) ? -1.0f : 1.0f;
    const float* fb = fold + (par ? FO_OFF : 0);

    // stage-2 assignment: k1 = t>>3, k2 group = (t&7)*4
    const int k1 = t >> 3;
    const int k2g = (t & 7) << 2;
    float c1, s1;
    sincospif((float)k1 * (1.0f / 128.0f), &s1, &c1);    // cis(2pi*k1/256)
    float c2 = 1.0f, s2 = 0.0f;                          // phase at x = 0
    ull A[4], B[4];
    {
        ull z; PACK2(z, 0.0f, 0.0f);
        #pragma unroll
        for (int j = 0; j < 4; ++j) { A[j] = z; B[j] = z; }
    }

    for (int chunk = 0; chunk < NCHUNK; ++chunk) {
        const int x0 = chunk * CROWS;

        // ---- load + fold 16 rows (1024 items, 4 per thread) ----
        #pragma unroll
        for (int i = t; i < CROWS * 64; i += 256) {
            const int r = i >> 6;
            const int y = i & 63;
            const float* row = src + (size_t)(x0 + r) * 256;
            if (y == 0) {
                const float a0 = row[0], a64 = row[64];
                const float a128 = row[128], a192 = row[192];
                spv[r] = make_float4(a0, a128, a64 + a192, a64 - a192);
            } else {
                const float a  = row[y];
                const float b  = row[128 - y];
                const float cc = row[128 + y];
                const float dd = row[256 - y];
                const float sA = a + dd, sB = b + cc;
                const float dA = a - dd, dB = b - cc;
                const int o = (r * 64 + y) * 2;
                *reinterpret_cast<float2*>(fold + o) =
                    make_float2(sA + sB, -(dA - dB));
                *reinterpret_cast<float2*>(fold + FO_OFF + o) =
                    make_float2(sA - sB, -(dA + dB));
            }
        }
        __syncthreads();

        // ---- stage 1: warp w -> rows rbase, rbase+1; lane = k2 ----
        {
            ull acc[2];
            #pragma unroll
            for (int j = 0; j < 2; ++j) {
                const float4 sp = spv[rbase + j];
                float ar, ai;
                if (par == 0) { ar = sp.x + sp.y + sg * sp.z; ai = 0.0f; }
                else          { ar = sp.x - sp.y;             ai = -sg * sp.w; }
                // y = 1 contribution (stored pre-negated d)
                const float2 v1 = *reinterpret_cast<const float2*>(
                    fb + ((rbase + j) * 64 + 1) * 2);
                ar = fmaf(v1.x, ck, ar);
                ai = fmaf(v1.y, sk, ai);
                PACK2(acc[j], ar, ai);
            }
            // dual phase recurrence: even y from 2, odd y from 3, step 2*theta
            float ce = c2k, se = s2k;                             // cis(2 theta)
            float co = fmaf(-sk, s2k, ck * c2k);                  // cis(3 theta)
            float so = fmaf(ck, s2k, sk * c2k);
            #pragma unroll 4
            for (int p = 1; p <= 31; ++p) {
                const int y = 2 * p;
                ull csE, csO;
                PACK2(csE, ce, se);
                PACK2(csO, co, so);
                #pragma unroll
                for (int j = 0; j < 2; ++j) {
                    const ulonglong2 v = *reinterpret_cast<const ulonglong2*>(
                        fb + ((rbase + j) * 64 + y) * 2);
                    FMA2(acc[j], v.x, csE, acc[j]);
                    FMA2(acc[j], v.y, csO, acc[j]);
                }
                const float ce_n = fmaf(-se, s2k, ce * c2k);
                se = fmaf(ce, s2k, se * c2k); ce = ce_n;
                const float co_n = fmaf(-so, s2k, co * c2k);
                so = fmaf(co, s2k, so * c2k); co = co_n;
            }
            #pragma unroll
            for (int j = 0; j < 2; ++j)
                *reinterpret_cast<ull*>(Gc + (rbase + j) * GC_STRIDE + lane * 2) = acc[j];
        }
        __syncthreads();

        // ---- stage 2 (partial over this chunk's 16 x values) ----
        #pragma unroll 4
        for (int xi = 0; xi < CROWS; ++xi) {
            ull cp, sp2;
            PACK2(cp, c2, c2);
            PACK2(sp2, s2, s2);
            const float* gp = Gc + xi * GC_STRIDE + k2g * 2;
            const ulonglong2 g01 = *reinterpret_cast<const ulonglong2*>(gp);
            const ulonglong2 g23 = *reinterpret_cast<const ulonglong2*>(gp + 4);
            FMA2(A[0], g01.x, cp, A[0]);  FMA2(B[0], g01.x, sp2, B[0]);
            FMA2(A[1], g01.y, cp, A[1]);  FMA2(B[1], g01.y, sp2, B[1]);
            FMA2(A[2], g23.x, cp, A[2]);  FMA2(B[2], g23.x, sp2, B[2]);
            FMA2(A[3], g23.y, cp, A[3]);  FMA2(B[3], g23.y, sp2, B[3]);
            const float cn = fmaf(-s2, s1, c2 * c1);
            s2 = fmaf(c2, s1, s2 * c1);
            c2 = cn;
        }
        __syncthreads();
    }

    // F = A - i*B : Fr = A.re + B.im, Fi = A.im - B.re
    const size_t base = (size_t)blk * NMODE + (size_t)k1 * 32 + k2g;
    #pragma unroll
    for (int j = 0; j < 4; ++j) {
        float Ar, Ai, Br, Bi;
        UNPACK2(Ar, Ai, A[j]);
        UNPACK2(Br, Bi, B[j]);
        g_modesR[base + j] = Ar + Bi;
        g_modesI[base + j] = Ai - Br;
    }
}

// ---------------------------------------------------------------------------
// Kernel 2: per-mode MLP + energies + errors + per-image normalization.
// One block per image (512 blocks, 256 threads, 4 modes/thread). FFMA2 inner.
// ---------------------------------------------------------------------------
__global__ __launch_bounds__(256) void mlp_kernel(
    const float* __restrict__ W1, const float* __restrict__ b1,
    const float* __restrict__ W2, const float* __restrict__ b2,
    const float* __restrict__ W3, const float* __restrict__ b3,
    float* __restrict__ out) {

    __shared__ float4 w1p[64];       // {W1[0][j], W1[1][j], b1[j], 0}
    __shared__ __align__(16) float W2s[64 * 32];
    __shared__ float  b2s[32];
    __shared__ float  W3s[32];
    __shared__ float  b3s;
    __shared__ float  red[256];

    const int t   = threadIdx.x;
    const int img = blockIdx.x;

    if (t < 64) w1p[t] = make_float4(W1[t], W1[64 + t], b1[t], 0.0f);
    for (int i = t; i < 2048; i += 256) W2s[i] = W2[i];
    if (t < 32) { b2s[t] = b2[t]; W3s[t] = W3[t]; }
    if (t == 0) b3s = b3[0];
    __syncthreads();

    const float* PR = g_modesR + (size_t)img * NMODE;
    const float* PI = g_modesI + (size_t)img * NMODE;
    const float* GR = g_modesR + (size_t)(NIMG + img) * NMODE;
    const float* GI = g_modesI + (size_t)(NIMG + img) * NMODE;

    float en[4], un[4];
    float esum = 0.0f;

    #pragma unroll
    for (int q = 0; q < 4; ++q) {
        const int m = t + q * 256;
        const float fr = PR[m];
        const float fi = PI[m];
        const float e  = fr * fr + fi * fi;
        en[q] = e;
        esum += e;

        // MLP: 2 -> 64 (relu) -> 32 (relu) -> 1 (softplus), packed accumulators
        ull acc[16];
        #pragma unroll
        for (int n = 0; n < 16; ++n) PACK2(acc[n], b2s[2 * n], b2s[2 * n + 1]);
        for (int j = 0; j < 64; ++j) {
            const float4 wp = w1p[j];
            float h = fmaf(fr, wp.x, fmaf(fi, wp.y, wp.z));
            h = fmaxf(h, 0.0f);
            ull hp; PACK2(hp, h, h);
            #pragma unroll
            for (int n4 = 0; n4 < 4; ++n4) {
                const ulonglong2 wv = *reinterpret_cast<const ulonglong2*>(
                    W2s + j * 32 + n4 * 8);
                const ulonglong2 wv2 = *reinterpret_cast<const ulonglong2*>(
                    W2s + j * 32 + n4 * 8 + 4);
                FMA2(acc[n4 * 4 + 0], wv.x,  hp, acc[n4 * 4 + 0]);
                FMA2(acc[n4 * 4 + 1], wv.y,  hp, acc[n4 * 4 + 1]);
                FMA2(acc[n4 * 4 + 2], wv2.x, hp, acc[n4 * 4 + 2]);
                FMA2(acc[n4 * 4 + 3], wv2.y, hp, acc[n4 * 4 + 3]);
            }
        }
        float o = b3s;
        #pragma unroll
        for (int n = 0; n < 16; ++n) {
            float a0, a1;
            UNPACK2(a0, a1, acc[n]);
            o = fmaf(fmaxf(a0, 0.0f), W3s[2 * n], o);
            o = fmaf(fmaxf(a1, 0.0f), W3s[2 * n + 1], o);
        }
        // softplus(o) = max(o,0) + log1p(exp(-|o|))
        const float u = fmaxf(o, 0.0f) + log1pf(expf(-fabsf(o)));
        un[q] = u;

        const float dr = fr - GR[m];
        const float di = fi - GI[m];
        const float err = dr * dr + di * di;

        const size_t base = (size_t)img * NMODE + m;
        out[OFF_E   + base] = e;
        out[OFF_U   + base] = u;
        out[OFF_ERR + base] = err;
    }

    // block reduce total modal energy
    red[t] = esum;
    __syncthreads();
    for (int st = 128; st > 0; st >>= 1) {
        if (t < st) red[t] += red[t + st];
        __syncthreads();
    }
    const float total = red[0] + EPS;

    #pragma unroll
    for (int q = 0; q < 4; ++q) {
        const int m = t + q * 256;
        const size_t base = (size_t)img * NMODE + m;
        const float frac = en[q] / total;
        out[OFF_F + base] = frac;
        out[OFF_W + base] = frac * un[q];
    }
}

// ---------------------------------------------------------------------------
// Kernel 3: per-mode reductions over the 512-image axis.
// ---------------------------------------------------------------------------
__global__ __launch_bounds__(128) void spec_kernel(float* __restrict__ out) {
    const int m = blockIdx.x;
    const int t = threadIdx.x;

    const float* U = out + OFF_U;
    const float* E = out + OFF_E;
    const float* R = out + OFF_ERR;

    double su = 0.0, se = 0.0, sr = 0.0, su2 = 0.0, sr2 = 0.0, sur = 0.0;
    for (int bc = t; bc < NIMG; bc += 128) {
        const size_t idx = (size_t)bc * NMODE + m;
        const double u = (double)U[idx];
        const double e = (double)E[idx];
        const double r = (double)R[idx];
        su += u; se += e; sr += r;
        su2 += u * u; sr2 += r * r; sur += u * r;
    }
    #pragma unroll
    for (int o = 16; o > 0; o >>= 1) {
        su  += __shfl_down_sync(0xffffffffu, su,  o);
        se  += __shfl_down_sync(0xffffffffu, se,  o);
        sr  += __shfl_down_sync(0xffffffffu, sr,  o);
        su2 += __shfl_down_sync(0xffffffffu, su2, o);
        sr2 += __shfl_down_sync(0xffffffffu, sr2, o);
        sur += __shfl_down_sync(0xffffffffu, sur, o);
    }
    __shared__ double sm[4][6];
    const int w = t >> 5, lane = t & 31;
    if (lane == 0) {
        sm[w][0] = su;  sm[w][1] = se;  sm[w][2] = sr;
        sm[w][3] = su2; sm[w][4] = sr2; sm[w][5] = sur;
    }
    __syncthreads();
    if (t == 0) {
        double a[6];
        #pragma unroll
        for (int i = 0; i < 6; ++i)
            a[i] = sm[0][i] + sm[1][i] + sm[2][i] + sm[3][i];
        const double n = (double)NIMG;
        out[OFF_US + m] = (float)(a[0] / n);
        out[OFF_ES + m] = (float)(a[1] / n);
        const double num = a[5] - a[0] * a[2] / n;
        const double vu  = a[3] - a[0] * a[0] / n;
        const double vr  = a[4] - a[2] * a[2] / n;
        const double den = sqrt(vu * vr);
        out[OFF_CAL + m] = (float)(num / (den + (double)EPS));
    }
}

// ---------------------------------------------------------------------------
// Launch — pure kernel launches, no attribute calls, no dynamic smem.
// ---------------------------------------------------------------------------
extern "C" void kernel_launch(void* const* d_in, const int* in_sizes, int n_in,
                              void* d_out, int out_size) {
    const float* pred = (const float*)d_in[0];
    const float* gt   = (const float*)d_in[2];
    const float* W1   = (const float*)d_in[3];
    const float* b1   = (const float*)d_in[4];
    const float* W2   = (const float*)d_in[5];
    const float* b2   = (const float*)d_in[6];
    const float* W3   = (const float*)d_in[7];
    const float* b3   = (const float*)d_in[8];
    float* out = (float*)d_out;

    fft_kernel<<<2 * NIMG, 256>>>(pred, gt);
    mlp_kernel<<<NIMG, 256>>>(W1, b1, W2, b2, W3, b3, out);
    spec_kernel<<<NMODE, 128>>>(out);
}